// round 16
// baseline (speedup 1.0000x reference)
#include <cuda_runtime.h>
#include <cuda_bf16.h>
#include <cuda_fp16.h>
#include <math.h>

#define NN 50000
#define EE 800000
#define HH 128
#define EPSBN 1e-5f

// packed f32x2 helpers (Blackwell FFMA2 path — PTX-only, ptxas won't fuse)
#define PACKDUP(d, f) asm("mov.b64 %0, {%1, %1};" : "=l"(d) : "r"(__float_as_uint(f)))
#define FMA2(a, x, y) asm("fma.rn.f32x2 %0, %1, %2, %0;" : "+l"(a) : "l"(x), "l"(y))
#define UNPK2(lo, hi, v) asm("mov.b64 {%0, %1}, %2;" : "=r"(lo), "=r"(hi) : "l"(v))

// ---------------- scratch (static device globals; no allocation) ------------
__device__ __half  g_h16[(size_t)NN * HH];   // 12.8 MB  h = x@W in fp16 (gather payload)
__device__ float   g_y[(size_t)NN * HH];     // 25.6 MB  post-activation layer output
__device__ float   g_als[NN];
__device__ float   g_ald[NN];
__device__ int     g_rp[NN + 1];             // CSR row ptr (by dst)
__device__ int     g_pos[NN];                // deg / cursors (reset by k_gemm layer 0)
__device__ float4  g_meta[EE];               // per CSR slot: ea0,ea1,ea2, src(int bits)
__device__ float   g_bnsum[3][HH];           // per-layer BN sums (reset by k_gemm[l])
__device__ float   g_bnsq[3][HH];
__device__ float   g_easum[3];               // (reset by k_hist)

// ---------------- histogram of in-degree + g_easum reset ---------------------
// g_pos is zeroed: static init on run 1, k_gemm layer 0 of the previous run after.
__global__ void k_hist(const int* __restrict__ dst, int e) {
    int i = blockIdx.x * blockDim.x + threadIdx.x;
    if (i < 3) g_easum[i] = 0.f;   // dead since last run's k_agg; k_fill refills next launch
    if (i < e) atomicAdd(&g_pos[dst[i]], 1);
}

// ---------------- exclusive scan (single block) -----------------------------
__global__ void k_scan(int n, int e) {
    __shared__ int chs[1024];
    int t = threadIdx.x;
    int per = (n + 1023) / 1024;
    int beg = t * per;
    int end = min(beg + per, n);
    int s = 0;
    for (int i = beg; i < end; i++) s += g_pos[i];
    chs[t] = s;
    __syncthreads();
    for (int off = 1; off < 1024; off <<= 1) {
        int v = (t >= off) ? chs[t - off] : 0;
        __syncthreads();
        chs[t] += v;
        __syncthreads();
    }
    int base = (t == 0) ? 0 : chs[t - 1];
    for (int i = beg; i < end; i++) {
        int d = g_pos[i];
        g_rp[i]  = base;
        g_pos[i] = base;   // cursor for fill
        base += d;
    }
    if (end == n) g_rp[n] = e;
}

// ---------------- scatter edges into CSR + partial sum of ea -----------------
__global__ void k_fill(const int* __restrict__ src, const int* __restrict__ dst,
                       const float* __restrict__ ea, int e) {
    int i = blockIdx.x * blockDim.x + threadIdx.x;
    float e0 = 0.f, e1 = 0.f, e2 = 0.f;
    if (i < e) {
        int s = src[i], d = dst[i];
        e0 = ea[3 * (size_t)i + 0];
        e1 = ea[3 * (size_t)i + 1];
        e2 = ea[3 * (size_t)i + 2];
        int k = atomicAdd(&g_pos[d], 1);
        g_meta[k] = make_float4(e0, e1, e2, __int_as_float(s));
    }
    for (int o = 16; o; o >>= 1) {
        e0 += __shfl_xor_sync(0xffffffffu, e0, o);
        e1 += __shfl_xor_sync(0xffffffffu, e1, o);
        e2 += __shfl_xor_sync(0xffffffffu, e2, o);
    }
    __shared__ float se[3];
    if (threadIdx.x < 3) se[threadIdx.x] = 0.f;
    __syncthreads();
    if ((threadIdx.x & 31) == 0) {
        atomicAdd(&se[0], e0);
        atomicAdd(&se[1], e1);
        atomicAdd(&se[2], e2);
    }
    __syncthreads();
    if (threadIdx.x < 3) atomicAdd(&g_easum[threadIdx.x], se[threadIdx.x]);
}

// ---------------- SGEMM  h = A(M,128) @ W(128,128)  + fused als/ald ----------
// FFMA2 mainloop; h stored fp16. layer>0: BN scale/shift of PREVIOUS layer is
// recomputed per block from g_bnsum[layer-1] (read-only here — no race).
// State resets (all on buffers dead at this point in the launch sequence):
//   layer 0 : g_pos (dead after k_fill; needed zero by next run's k_hist)
//   layer l : g_bnsum[l]/g_bnsq[l] via block 0 (consumed by gemm[l+1]/final of
//             the PREVIOUS run; k_agg[l] accumulates in the NEXT launch)
__global__ void __launch_bounds__(256) k_gemm(const float* __restrict__ Ax,
                                              const float* __restrict__ W,
                                              const float* __restrict__ as_,
                                              const float* __restrict__ ad_,
                                              const float* __restrict__ gamma,
                                              const float* __restrict__ beta,
                                              int M, int n, int layer) {
    __shared__ float As[8][128];
    __shared__ float Bs[8][128];
    __shared__ float sscale[128], sshift[128];
    int tid  = threadIdx.x;
    int brow = blockIdx.x * 128;
    int gi   = blockIdx.x * 256 + tid;
    // ---- state resets (no consumer of these buffers is in flight) ----
    if (layer == 0) {
        if (gi < n) g_pos[gi] = 0;
    }
    if (blockIdx.x == 0 && tid < 128) {
        g_bnsum[layer][tid] = 0.f;
        g_bnsq[layer][tid]  = 0.f;
    }
    int tx = tid & 15, ty = tid >> 4;
    int la_row = tid >> 1;
    int la_k4  = (tid & 1) * 4;
    int lb_k   = tid >> 5;
    int lb_c   = (tid & 31) * 4;
    int use_bn = layer > 0;
    if (use_bn && tid < 128) {
        float invn = 1.f / (float)n;
        float mu  = g_bnsum[layer - 1][tid] * invn;
        float var = g_bnsq[layer - 1][tid] * invn - mu * mu;
        float sc  = rsqrtf(var + EPSBN) * gamma[tid];
        sscale[tid] = sc;
        sshift[tid] = beta[tid] - mu * sc;
    }
    if (use_bn) __syncthreads();
    const float* A = use_bn ? (const float*)g_y : Ax;
    unsigned long long acc2[8][4];
#pragma unroll
    for (int i = 0; i < 8; i++)
#pragma unroll
        for (int j = 0; j < 4; j++) acc2[i][j] = 0ull;

    for (int kb = 0; kb < 128; kb += 8) {
        float4 av = make_float4(0.f, 0.f, 0.f, 0.f);
        int ar = brow + la_row;
        if (ar < M) av = *(const float4*)(A + (size_t)ar * 128 + kb + la_k4);
        if (use_bn) {
            int kk = kb + la_k4;
            av.x = fmaf(av.x, sscale[kk + 0], sshift[kk + 0]);
            av.y = fmaf(av.y, sscale[kk + 1], sshift[kk + 1]);
            av.z = fmaf(av.z, sscale[kk + 2], sshift[kk + 2]);
            av.w = fmaf(av.w, sscale[kk + 3], sshift[kk + 3]);
        }
        As[la_k4 + 0][la_row] = av.x;
        As[la_k4 + 1][la_row] = av.y;
        As[la_k4 + 2][la_row] = av.z;
        As[la_k4 + 3][la_row] = av.w;
        *(float4*)&Bs[lb_k][lb_c] = *(const float4*)(W + (size_t)(kb + lb_k) * 128 + lb_c);
        __syncthreads();
#pragma unroll
        for (int k = 0; k < 8; k++) {
            float4 a0 = *(const float4*)&As[k][ty * 8];
            float4 a1 = *(const float4*)&As[k][ty * 8 + 4];
            unsigned long long ra2[8];
            PACKDUP(ra2[0], a0.x); PACKDUP(ra2[1], a0.y);
            PACKDUP(ra2[2], a0.z); PACKDUP(ra2[3], a0.w);
            PACKDUP(ra2[4], a1.x); PACKDUP(ra2[5], a1.y);
            PACKDUP(ra2[6], a1.z); PACKDUP(ra2[7], a1.w);
            unsigned long long rb2[4];
#pragma unroll
            for (int j = 0; j < 4; j++)
                rb2[j] = *(const unsigned long long*)&Bs[k][2 * tx + 32 * j];
#pragma unroll
            for (int i = 0; i < 8; i++)
#pragma unroll
                for (int j = 0; j < 4; j++)
                    FMA2(acc2[i][j], ra2[i], rb2[j]);
        }
        __syncthreads();
    }

    // store h as fp16: packed pair (col 2tx+32j, col 2tx+1+32j) -> __half2
#pragma unroll
    for (int i = 0; i < 8; i++) {
        int r = brow + ty * 8 + i;
        if (r < M) {
            __half* hr = g_h16 + (size_t)r * 128 + 2 * tx;
#pragma unroll
            for (int j = 0; j < 4; j++) {
                unsigned int lo, hi;
                UNPK2(lo, hi, acc2[i][j]);
                *(__half2*)(hr + 32 * j) =
                    __floats2half2_rn(__uint_as_float(lo), __uint_as_float(hi));
            }
        }
    }

    // fused als/ald (f32x2 dot, EXACT fp32 h), reduced over the 16 tx-lanes
    unsigned long long as2[4], ad2[4];
#pragma unroll
    for (int j = 0; j < 4; j++) {
        as2[j] = *(const unsigned long long*)(as_ + 2 * tx + 32 * j);
        ad2[j] = *(const unsigned long long*)(ad_ + 2 * tx + 32 * j);
    }
#pragma unroll
    for (int i = 0; i < 8; i++) {
        unsigned long long ps2 = 0ull, pd2 = 0ull;
#pragma unroll
        for (int j = 0; j < 4; j++) {
            FMA2(ps2, acc2[i][j], as2[j]);
            FMA2(pd2, acc2[i][j], ad2[j]);
        }
        unsigned int lo, hi;
        UNPK2(lo, hi, ps2);
        float ps = __uint_as_float(lo) + __uint_as_float(hi);
        UNPK2(lo, hi, pd2);
        float pd = __uint_as_float(lo) + __uint_as_float(hi);
#pragma unroll
        for (int o = 8; o; o >>= 1) {
            ps += __shfl_xor_sync(0xffffffffu, ps, o);
            pd += __shfl_xor_sync(0xffffffffu, pd, o);
        }
        int r = brow + ty * 8 + i;
        if (tx == 0 && r < M) { g_als[r] = ps; g_ald[r] = pd; }
    }
}

// ---------------- warp-per-node aggregation, UNNORMALIZED softmax ------------
// ve (We@ae, ale_self) computed per-block by warp 0. h gathered in fp16 (one
// LDG.64 per lane per edge); coefficients exact fp32. BN partials accumulate
// into g_bnsum[layer] (zeroed by k_gemm[layer] one launch earlier).
__global__ void __launch_bounds__(512) k_agg(const float* __restrict__ bias,
                                             const float* __restrict__ We,
                                             const float* __restrict__ ae,
                                             int n, int e, int layer) {
    __shared__ float2 sstage[16][128];    // staging: (ev, src-bits); later: (v, v*v)
    __shared__ float sve[4];
    int t = threadIdx.x;
    int warp = t >> 5, lane = t & 31;

    // warp 0: ve = We @ ae (3 dots of 128) + ale_self
    if (warp == 0) {
        float s0 = 0.f, s1 = 0.f, s2 = 0.f;
#pragma unroll
        for (int q = 0; q < 4; q++) {
            float aev = ae[lane + 32 * q];
            s0 = fmaf(We[0 * 128 + lane + 32 * q], aev, s0);
            s1 = fmaf(We[1 * 128 + lane + 32 * q], aev, s1);
            s2 = fmaf(We[2 * 128 + lane + 32 * q], aev, s2);
        }
        for (int o = 16; o; o >>= 1) {
            s0 += __shfl_xor_sync(0xffffffffu, s0, o);
            s1 += __shfl_xor_sync(0xffffffffu, s1, o);
            s2 += __shfl_xor_sync(0xffffffffu, s2, o);
        }
        if (lane == 0) {
            float inv_e = 1.f / (float)e;
            sve[0] = s0; sve[1] = s1; sve[2] = s2;
            sve[3] = (g_easum[0] * inv_e) * s0 +
                     (g_easum[1] * inv_e) * s1 +
                     (g_easum[2] * inv_e) * s2;
        }
    }
    __syncthreads();

    int i = blockIdx.x * 16 + warp;
    float ve0 = sve[0], ve1 = sve[1], ve2 = sve[2], aself = sve[3];
    float4 v = make_float4(0.f, 0.f, 0.f, 0.f);
    if (i < n) {
        // hoisted self-row load (fp16) — overlaps with staging below
        uint2 us = *(const uint2*)(g_h16 + (size_t)i * 128 + lane * 4);
        float2 hs0 = __half22float2(*(__half2*)&us.x);
        float2 hs1 = __half22float2(*(__half2*)&us.y);

        float adi = g_ald[i];
        float sa  = g_als[i] + adi + aself;
        sa = sa > 0.f ? sa : 0.2f * sa;
        float evself = __expf(sa);
        int k0 = g_rp[i], k1 = g_rp[i + 1];

        float4 num = make_float4(0.f, 0.f, 0.f, 0.f);
        float den = 0.f;

        for (int base = k0; base < k1; base += 128) {
            int cend = min(128, k1 - base);
#pragma unroll
            for (int it = 0; it < 4; it++) {
                int k = base + it * 32 + lane;
                if (it * 32 + lane < cend) {
                    float4 mt = g_meta[k];
                    int s = __float_as_int(mt.w);
                    float a = g_als[s] + adi + mt.x * ve0 + mt.y * ve1 + mt.z * ve2;
                    a = a > 0.f ? a : 0.2f * a;
                    sstage[warp][it * 32 + lane] = make_float2(__expf(a), mt.w);
                }
            }
            __syncwarp();
            // gather: lane owns features 4*lane..4*lane+3 (fp16, LDG.64)
#pragma unroll 8
            for (int j = 0; j < cend; j++) {
                float2 st = sstage[warp][j];
                float cj = st.x;
                int   sj = __float_as_int(st.y);
                uint2 u = *(const uint2*)(g_h16 + (size_t)sj * 128 + lane * 4);
                float2 f0 = __half22float2(*(__half2*)&u.x);
                float2 f1 = __half22float2(*(__half2*)&u.y);
                num.x = fmaf(cj, f0.x, num.x);
                num.y = fmaf(cj, f0.y, num.y);
                num.z = fmaf(cj, f1.x, num.z);
                num.w = fmaf(cj, f1.y, num.w);
                den += cj;
            }
            if (base + 128 < k1) __syncwarp();
        }

        // add self contribution and normalize
        num.x = fmaf(evself, hs0.x, num.x);
        num.y = fmaf(evself, hs0.y, num.y);
        num.z = fmaf(evself, hs1.x, num.z);
        num.w = fmaf(evself, hs1.y, num.w);
        den += evself;
        float inv = 1.f / (den + 1e-16f);

        // epilogue: normalize, + bias, leaky 0.01, store y
        float4 b4 = *(const float4*)(bias + lane * 4);
        v.x = fmaf(num.x, inv, b4.x); v.x = v.x > 0.f ? v.x : 0.01f * v.x;
        v.y = fmaf(num.y, inv, b4.y); v.y = v.y > 0.f ? v.y : 0.01f * v.y;
        v.z = fmaf(num.z, inv, b4.z); v.z = v.z > 0.f ? v.z : 0.01f * v.z;
        v.w = fmaf(num.w, inv, b4.w); v.w = v.w > 0.f ? v.w : 0.01f * v.w;
        *(float4*)(g_y + (size_t)i * 128 + lane * 4) = v;
    }

    // ---- BN partial reduction into this layer's buffer ----
    __syncthreads();
    sstage[warp][lane * 4 + 0] = make_float2(v.x, v.x * v.x);
    sstage[warp][lane * 4 + 1] = make_float2(v.y, v.y * v.y);
    sstage[warp][lane * 4 + 2] = make_float2(v.z, v.z * v.z);
    sstage[warp][lane * 4 + 3] = make_float2(v.w, v.w * v.w);
    __syncthreads();
    if (t < 128) {
        float s = 0.f, q = 0.f;
#pragma unroll
        for (int w = 0; w < 16; w++) {
            float2 e2 = sstage[w][t];
            s += e2.x; q += e2.y;
        }
        atomicAdd(&g_bnsum[layer][t], s);
        atomicAdd(&g_bnsq[layer][t],  q);
    }
}

// ---------------- final: layer-3 BN (per-block stats, READ-ONLY) -------------
__global__ void k_final(float4* __restrict__ out,
                        const float* __restrict__ gamma,
                        const float* __restrict__ beta,
                        int n, int total4) {
    __shared__ float s_sc[128], s_sh[128];
    int t = threadIdx.x;
    if (t < 128) {
        float invn = 1.f / (float)n;
        float mu  = g_bnsum[2][t] * invn;
        float var = g_bnsq[2][t] * invn - mu * mu;
        float sc  = rsqrtf(var + EPSBN) * gamma[t];
        s_sc[t] = sc;
        s_sh[t] = beta[t] - mu * sc;
    }
    __syncthreads();
    int i = blockIdx.x * blockDim.x + t;
    if (i < total4) {
        int f = (i & 31) * 4;
        float4 y = ((const float4*)g_y)[i];
        float4 o;
        o.x = fmaf(y.x, s_sc[f + 0], s_sh[f + 0]);
        o.y = fmaf(y.y, s_sc[f + 1], s_sh[f + 1]);
        o.z = fmaf(y.z, s_sc[f + 2], s_sh[f + 2]);
        o.w = fmaf(y.w, s_sc[f + 3], s_sh[f + 3]);
        out[i] = o;
    }
    // NO resets here — every accumulator is zeroed by its producer-side kernel
    // (k_hist: g_easum, k_gemm[0]: g_pos, k_gemm[l]: g_bnsum/bnsq[l]) at a
    // point where no consumer is in flight.
}

// ---------------- launch ----------------------------------------------------
extern "C" void kernel_launch(void* const* d_in, const int* in_sizes, int n_in,
                              void* d_out, int out_size) {
    const float* x    = (const float*)d_in[0];
    const int*   eidx = (const int*)d_in[1];
    const float* ea   = (const float*)d_in[3];
    int n = in_sizes[0] / 128;
    int e = in_sizes[3] / 3;
    const int* src = eidx;
    const int* dst = eidx + e;

    const float *W[3], *as_[3], *ad_[3], *We[3], *ae[3], *b[3], *g[3], *be[3];
    for (int l = 0; l < 3; l++) {
        int base = 4 + 8 * l;
        W[l]   = (const float*)d_in[base + 0];
        as_[l] = (const float*)d_in[base + 1];
        ad_[l] = (const float*)d_in[base + 2];
        We[l]  = (const float*)d_in[base + 3];
        ae[l]  = (const float*)d_in[base + 4];
        b[l]   = (const float*)d_in[base + 5];
        g[l]   = (const float*)d_in[base + 6];
        be[l]  = (const float*)d_in[base + 7];
    }
    float* out = (float*)d_out;

    int gE = (e + 255) / 256;

    k_hist<<<gE, 256>>>(dst, e);
    k_scan<<<1, 1024>>>(n, e);
    k_fill<<<gE, 256>>>(src, dst, ea, e);

    for (int l = 0; l < 3; l++) {
        k_gemm<<<(n + 127) / 128, 256>>>(x, W[l], as_[l], ad_[l],
                                         l > 0 ? g[l - 1] : (const float*)0,
                                         l > 0 ? be[l - 1] : (const float*)0,
                                         n, n, l);
        k_agg<<<(n + 15) / 16, 512>>>(b[l], We[l], ae[l], n, e, l);
    }
    k_final<<<(n * 32 + 255) / 256, 256>>>((float4*)out, g[2], be[2], n, n * 32);
}

// round 17
// speedup vs baseline: 1.3865x; 1.3865x over previous
#include <cuda_runtime.h>
#include <cuda_bf16.h>
#include <math.h>

#define NN 50000
#define EE 800000
#define HH 128
#define EPSBN 1e-5f

// packed f32x2 helpers (Blackwell FFMA2 path — PTX-only, ptxas won't fuse)
#define PACKDUP(d, f) asm("mov.b64 %0, {%1, %1};" : "=l"(d) : "r"(__float_as_uint(f)))
#define FMA2(a, x, y) asm("fma.rn.f32x2 %0, %1, %2, %0;" : "+l"(a) : "l"(x), "l"(y))
#define UNPK2(lo, hi, v) asm("mov.b64 {%0, %1}, %2;" : "=r"(lo), "=r"(hi) : "l"(v))

// ---------------- scratch (static device globals; no allocation) ------------
__device__ float   g_h[(size_t)NN * HH];     // 25.6 MB  h = x@W (fp32 — exact)
__device__ float   g_y[(size_t)NN * HH];     // 25.6 MB  post-activation layer output
__device__ float   g_als[NN];
__device__ float   g_ald[NN];
__device__ int     g_rp[NN + 1];             // CSR row ptr (by dst)
__device__ int     g_pos[NN];                // deg / cursors (reset by k_gemm layer 0)
__device__ float4  g_meta[EE];               // per CSR slot: ea0,ea1,ea2, src(int bits)
__device__ float   g_bnsum[3][HH];           // per-layer BN sums (reset by k_gemm[l])
__device__ float   g_bnsq[3][HH];
__device__ float   g_easum[3];               // (reset by k_hist)

// ---------------- histogram of in-degree + g_easum reset ---------------------
__global__ void k_hist(const int* __restrict__ dst, int e) {
    int i = blockIdx.x * blockDim.x + threadIdx.x;
    if (i < 3) g_easum[i] = 0.f;   // dead since last run's k_agg; k_fill refills next launch
    if (i < e) atomicAdd(&g_pos[dst[i]], 1);
}

// ---------------- exclusive scan (single block) -----------------------------
__global__ void k_scan(int n, int e) {
    __shared__ int chs[1024];
    int t = threadIdx.x;
    int per = (n + 1023) / 1024;
    int beg = t * per;
    int end = min(beg + per, n);
    int s = 0;
    for (int i = beg; i < end; i++) s += g_pos[i];
    chs[t] = s;
    __syncthreads();
    for (int off = 1; off < 1024; off <<= 1) {
        int v = (t >= off) ? chs[t - off] : 0;
        __syncthreads();
        chs[t] += v;
        __syncthreads();
    }
    int base = (t == 0) ? 0 : chs[t - 1];
    for (int i = beg; i < end; i++) {
        int d = g_pos[i];
        g_rp[i]  = base;
        g_pos[i] = base;   // cursor for fill
        base += d;
    }
    if (end == n) g_rp[n] = e;
}

// ---------------- scatter edges into CSR + partial sum of ea -----------------
__global__ void k_fill(const int* __restrict__ src, const int* __restrict__ dst,
                       const float* __restrict__ ea, int e) {
    int i = blockIdx.x * blockDim.x + threadIdx.x;
    float e0 = 0.f, e1 = 0.f, e2 = 0.f;
    if (i < e) {
        int s = src[i], d = dst[i];
        e0 = ea[3 * (size_t)i + 0];
        e1 = ea[3 * (size_t)i + 1];
        e2 = ea[3 * (size_t)i + 2];
        int k = atomicAdd(&g_pos[d], 1);
        g_meta[k] = make_float4(e0, e1, e2, __int_as_float(s));
    }
    for (int o = 16; o; o >>= 1) {
        e0 += __shfl_xor_sync(0xffffffffu, e0, o);
        e1 += __shfl_xor_sync(0xffffffffu, e1, o);
        e2 += __shfl_xor_sync(0xffffffffu, e2, o);
    }
    __shared__ float se[3];
    if (threadIdx.x < 3) se[threadIdx.x] = 0.f;
    __syncthreads();
    if ((threadIdx.x & 31) == 0) {
        atomicAdd(&se[0], e0);
        atomicAdd(&se[1], e1);
        atomicAdd(&se[2], e2);
    }
    __syncthreads();
    if (threadIdx.x < 3) atomicAdd(&g_easum[threadIdx.x], se[threadIdx.x]);
}

// ---------------- SGEMM  h = A(M,128) @ W(128,128)  + fused als/ald ----------
// FFMA2 mainloop, retiled for OCCUPANCY: 64x128 CTA tile, 256 threads, each
// thread 4 rows x 4 column-pairs -> 16 b64 accumulators (~63 regs, 3-4 CTAs/SM
// vs 2 before). Per k-step: 1 LDS.128 + 4 PACKDUP + 4 LDS.64 + 16 FMA2.
// layer>0: BN scale/shift of PREVIOUS layer recomputed per block (read-only).
// State resets (buffers dead at this point in the launch sequence):
//   layer 0 : g_pos ; layer l : g_bnsum[l]/g_bnsq[l] via block 0.
__global__ void __launch_bounds__(256, 3) k_gemm(const float* __restrict__ Ax,
                                                 const float* __restrict__ W,
                                                 const float* __restrict__ as_,
                                                 const float* __restrict__ ad_,
                                                 const float* __restrict__ gamma,
                                                 const float* __restrict__ beta,
                                                 int M, int n, int layer) {
    __shared__ float As[8][64];
    __shared__ float Bs[8][128];
    __shared__ float sscale[128], sshift[128];
    int tid  = threadIdx.x;
    int brow = blockIdx.x * 64;
    int gi   = blockIdx.x * 256 + tid;
    // ---- state resets (no consumer of these buffers is in flight) ----
    if (layer == 0) {
        if (gi < n) g_pos[gi] = 0;
    }
    if (blockIdx.x == 0 && tid < 128) {
        g_bnsum[layer][tid] = 0.f;
        g_bnsq[layer][tid]  = 0.f;
    }
    int tx = tid & 15, ty = tid >> 4;
    int la_row = tid >> 1;          // 0..127 (only tid<128 -> rows 0..63 load A)
    int la_k4  = (tid & 1) * 4;
    int lb_k   = tid >> 5;
    int lb_c   = (tid & 31) * 4;
    int use_bn = layer > 0;
    if (use_bn && tid < 128) {
        float invn = 1.f / (float)n;
        float mu  = g_bnsum[layer - 1][tid] * invn;
        float var = g_bnsq[layer - 1][tid] * invn - mu * mu;
        float sc  = rsqrtf(var + EPSBN) * gamma[tid];
        sscale[tid] = sc;
        sshift[tid] = beta[tid] - mu * sc;
    }
    if (use_bn) __syncthreads();
    const float* A = use_bn ? (const float*)g_y : Ax;
    unsigned long long acc2[4][4];
#pragma unroll
    for (int i = 0; i < 4; i++)
#pragma unroll
        for (int j = 0; j < 4; j++) acc2[i][j] = 0ull;

    for (int kb = 0; kb < 128; kb += 8) {
        if (tid < 128) {
            float4 av = make_float4(0.f, 0.f, 0.f, 0.f);
            int ar = brow + la_row;
            if (ar < M) av = *(const float4*)(A + (size_t)ar * 128 + kb + la_k4);
            if (use_bn) {
                int kk = kb + la_k4;
                av.x = fmaf(av.x, sscale[kk + 0], sshift[kk + 0]);
                av.y = fmaf(av.y, sscale[kk + 1], sshift[kk + 1]);
                av.z = fmaf(av.z, sscale[kk + 2], sshift[kk + 2]);
                av.w = fmaf(av.w, sscale[kk + 3], sshift[kk + 3]);
            }
            As[la_k4 + 0][la_row] = av.x;
            As[la_k4 + 1][la_row] = av.y;
            As[la_k4 + 2][la_row] = av.z;
            As[la_k4 + 3][la_row] = av.w;
        }
        *(float4*)&Bs[lb_k][lb_c] = *(const float4*)(W + (size_t)(kb + lb_k) * 128 + lb_c);
        __syncthreads();
#pragma unroll
        for (int k = 0; k < 8; k++) {
            float4 a0 = *(const float4*)&As[k][ty * 4];
            unsigned long long ra2[4];
            PACKDUP(ra2[0], a0.x); PACKDUP(ra2[1], a0.y);
            PACKDUP(ra2[2], a0.z); PACKDUP(ra2[3], a0.w);
            unsigned long long rb2[4];
#pragma unroll
            for (int j = 0; j < 4; j++)
                rb2[j] = *(const unsigned long long*)&Bs[k][2 * tx + 32 * j];
#pragma unroll
            for (int i = 0; i < 4; i++)
#pragma unroll
                for (int j = 0; j < 4; j++)
                    FMA2(acc2[i][j], ra2[i], rb2[j]);
        }
        __syncthreads();
    }

    // store h (fp32): packed b64 = cols (2tx+32j, 2tx+1+32j), row-major layout
#pragma unroll
    for (int i = 0; i < 4; i++) {
        int r = brow + ty * 4 + i;
        if (r < M) {
            float* hr = g_h + (size_t)r * 128 + 2 * tx;
#pragma unroll
            for (int j = 0; j < 4; j++)
                *(unsigned long long*)(hr + 32 * j) = acc2[i][j];
        }
    }

    // fused als/ald (f32x2 dot), reduced over the 16 tx-lanes (xor 8,4,2,1
    // stays within the tx nibble; both ty-halves of the warp reduce in parallel)
    unsigned long long as2[4], ad2[4];
#pragma unroll
    for (int j = 0; j < 4; j++) {
        as2[j] = *(const unsigned long long*)(as_ + 2 * tx + 32 * j);
        ad2[j] = *(const unsigned long long*)(ad_ + 2 * tx + 32 * j);
    }
#pragma unroll
    for (int i = 0; i < 4; i++) {
        unsigned long long ps2 = 0ull, pd2 = 0ull;
#pragma unroll
        for (int j = 0; j < 4; j++) {
            FMA2(ps2, acc2[i][j], as2[j]);
            FMA2(pd2, acc2[i][j], ad2[j]);
        }
        unsigned int lo, hi;
        UNPK2(lo, hi, ps2);
        float ps = __uint_as_float(lo) + __uint_as_float(hi);
        UNPK2(lo, hi, pd2);
        float pd = __uint_as_float(lo) + __uint_as_float(hi);
#pragma unroll
        for (int o = 8; o; o >>= 1) {
            ps += __shfl_xor_sync(0xffffffffu, ps, o);
            pd += __shfl_xor_sync(0xffffffffu, pd, o);
        }
        int r = brow + ty * 4 + i;
        if (tx == 0 && r < M) { g_als[r] = ps; g_ald[r] = pd; }
    }
}

// ---------------- warp-per-node aggregation, UNNORMALIZED softmax ------------
// ve (We@ae, ale_self) computed per-block by warp 0. fp32 gather: one LDG.128
// per lane per edge. BN partials accumulate into g_bnsum[layer] (zeroed by
// k_gemm[layer] one launch earlier).
__global__ void __launch_bounds__(512) k_agg(const float* __restrict__ bias,
                                             const float* __restrict__ We,
                                             const float* __restrict__ ae,
                                             int n, int e, int layer) {
    __shared__ float2 sstage[16][128];    // staging: (ev, src-bits); later: (v, v*v)
    __shared__ float sve[4];
    int t = threadIdx.x;
    int warp = t >> 5, lane = t & 31;

    // warp 0: ve = We @ ae (3 dots of 128) + ale_self
    if (warp == 0) {
        float s0 = 0.f, s1 = 0.f, s2 = 0.f;
#pragma unroll
        for (int q = 0; q < 4; q++) {
            float aev = ae[lane + 32 * q];
            s0 = fmaf(We[0 * 128 + lane + 32 * q], aev, s0);
            s1 = fmaf(We[1 * 128 + lane + 32 * q], aev, s1);
            s2 = fmaf(We[2 * 128 + lane + 32 * q], aev, s2);
        }
        for (int o = 16; o; o >>= 1) {
            s0 += __shfl_xor_sync(0xffffffffu, s0, o);
            s1 += __shfl_xor_sync(0xffffffffu, s1, o);
            s2 += __shfl_xor_sync(0xffffffffu, s2, o);
        }
        if (lane == 0) {
            float inv_e = 1.f / (float)e;
            sve[0] = s0; sve[1] = s1; sve[2] = s2;
            sve[3] = (g_easum[0] * inv_e) * s0 +
                     (g_easum[1] * inv_e) * s1 +
                     (g_easum[2] * inv_e) * s2;
        }
    }
    __syncthreads();

    int i = blockIdx.x * 16 + warp;
    float ve0 = sve[0], ve1 = sve[1], ve2 = sve[2], aself = sve[3];
    float4 v = make_float4(0.f, 0.f, 0.f, 0.f);
    if (i < n) {
        // hoisted self-row load — overlaps with staging below
        float4 hv = *(const float4*)(g_h + (size_t)i * 128 + lane * 4);

        float adi = g_ald[i];
        float sa  = g_als[i] + adi + aself;
        sa = sa > 0.f ? sa : 0.2f * sa;
        float evself = __expf(sa);
        int k0 = g_rp[i], k1 = g_rp[i + 1];

        float4 num = make_float4(0.f, 0.f, 0.f, 0.f);
        float den = 0.f;

        for (int base = k0; base < k1; base += 128) {
            int cend = min(128, k1 - base);
#pragma unroll
            for (int it = 0; it < 4; it++) {
                int k = base + it * 32 + lane;
                if (it * 32 + lane < cend) {
                    float4 mt = g_meta[k];
                    int s = __float_as_int(mt.w);
                    float a = g_als[s] + adi + mt.x * ve0 + mt.y * ve1 + mt.z * ve2;
                    a = a > 0.f ? a : 0.2f * a;
                    sstage[warp][it * 32 + lane] = make_float2(__expf(a), mt.w);
                }
            }
            __syncwarp();
            // gather: lane owns features 4*lane..4*lane+3 (fp32, LDG.128)
#pragma unroll 8
            for (int j = 0; j < cend; j++) {
                float2 st = sstage[warp][j];
                float cj = st.x;
                int   sj = __float_as_int(st.y);
                float4 hp = *(const float4*)(g_h + (size_t)sj * 128 + lane * 4);
                num.x = fmaf(cj, hp.x, num.x);
                num.y = fmaf(cj, hp.y, num.y);
                num.z = fmaf(cj, hp.z, num.z);
                num.w = fmaf(cj, hp.w, num.w);
                den += cj;
            }
            if (base + 128 < k1) __syncwarp();
        }

        // add self contribution and normalize
        num.x = fmaf(evself, hv.x, num.x);
        num.y = fmaf(evself, hv.y, num.y);
        num.z = fmaf(evself, hv.z, num.z);
        num.w = fmaf(evself, hv.w, num.w);
        den += evself;
        float inv = 1.f / (den + 1e-16f);

        // epilogue: normalize, + bias, leaky 0.01, store y
        float4 b4 = *(const float4*)(bias + lane * 4);
        v.x = fmaf(num.x, inv, b4.x); v.x = v.x > 0.f ? v.x : 0.01f * v.x;
        v.y = fmaf(num.y, inv, b4.y); v.y = v.y > 0.f ? v.y : 0.01f * v.y;
        v.z = fmaf(num.z, inv, b4.z); v.z = v.z > 0.f ? v.z : 0.01f * v.z;
        v.w = fmaf(num.w, inv, b4.w); v.w = v.w > 0.f ? v.w : 0.01f * v.w;
        *(float4*)(g_y + (size_t)i * 128 + lane * 4) = v;
    }

    // ---- BN partial reduction into this layer's buffer ----
    __syncthreads();
    sstage[warp][lane * 4 + 0] = make_float2(v.x, v.x * v.x);
    sstage[warp][lane * 4 + 1] = make_float2(v.y, v.y * v.y);
    sstage[warp][lane * 4 + 2] = make_float2(v.z, v.z * v.z);
    sstage[warp][lane * 4 + 3] = make_float2(v.w, v.w * v.w);
    __syncthreads();
    if (t < 128) {
        float s = 0.f, q = 0.f;
#pragma unroll
        for (int w = 0; w < 16; w++) {
            float2 e2 = sstage[w][t];
            s += e2.x; q += e2.y;
        }
        atomicAdd(&g_bnsum[layer][t], s);
        atomicAdd(&g_bnsq[layer][t],  q);
    }
}

// ---------------- final: layer-3 BN (per-block stats, READ-ONLY) -------------
__global__ void k_final(float4* __restrict__ out,
                        const float* __restrict__ gamma,
                        const float* __restrict__ beta,
                        int n, int total4) {
    __shared__ float s_sc[128], s_sh[128];
    int t = threadIdx.x;
    if (t < 128) {
        float invn = 1.f / (float)n;
        float mu  = g_bnsum[2][t] * invn;
        float var = g_bnsq[2][t] * invn - mu * mu;
        float sc  = rsqrtf(var + EPSBN) * gamma[t];
        s_sc[t] = sc;
        s_sh[t] = beta[t] - mu * sc;
    }
    __syncthreads();
    int i = blockIdx.x * blockDim.x + t;
    if (i < total4) {
        int f = (i & 31) * 4;
        float4 y = ((const float4*)g_y)[i];
        float4 o;
        o.x = fmaf(y.x, s_sc[f + 0], s_sh[f + 0]);
        o.y = fmaf(y.y, s_sc[f + 1], s_sh[f + 1]);
        o.z = fmaf(y.z, s_sc[f + 2], s_sh[f + 2]);
        o.w = fmaf(y.w, s_sc[f + 3], s_sh[f + 3]);
        out[i] = o;
    }
    // NO resets here — accumulators are zeroed by their producer-side kernels
    // at points where no consumer is in flight.
}

// ---------------- launch ----------------------------------------------------
extern "C" void kernel_launch(void* const* d_in, const int* in_sizes, int n_in,
                              void* d_out, int out_size) {
    const float* x    = (const float*)d_in[0];
    const int*   eidx = (const int*)d_in[1];
    const float* ea   = (const float*)d_in[3];
    int n = in_sizes[0] / 128;
    int e = in_sizes[3] / 3;
    const int* src = eidx;
    const int* dst = eidx + e;

    const float *W[3], *as_[3], *ad_[3], *We[3], *ae[3], *b[3], *g[3], *be[3];
    for (int l = 0; l < 3; l++) {
        int base = 4 + 8 * l;
        W[l]   = (const float*)d_in[base + 0];
        as_[l] = (const float*)d_in[base + 1];
        ad_[l] = (const float*)d_in[base + 2];
        We[l]  = (const float*)d_in[base + 3];
        ae[l]  = (const float*)d_in[base + 4];
        b[l]   = (const float*)d_in[base + 5];
        g[l]   = (const float*)d_in[base + 6];
        be[l]  = (const float*)d_in[base + 7];
    }
    float* out = (float*)d_out;

    int gE = (e + 255) / 256;

    k_hist<<<gE, 256>>>(dst, e);
    k_scan<<<1, 1024>>>(n, e);
    k_fill<<<gE, 256>>>(src, dst, ea, e);

    for (int l = 0; l < 3; l++) {
        k_gemm<<<(n + 63) / 64, 256>>>(x, W[l], as_[l], ad_[l],
                                       l > 0 ? g[l - 1] : (const float*)0,
                                       l > 0 ? be[l - 1] : (const float*)0,
                                       n, n, l);
        k_agg<<<(n + 15) / 16, 512>>>(b[l], We[l], ae[l], n, e, l);
    }
    k_final<<<(n * 32 + 255) / 256, 256>>>((float4*)out, g[2], be[2], n, n * 32);
}